// round 16
// baseline (speedup 1.0000x reference)
#include <cuda_runtime.h>
#include <cuda_bf16.h>
#include <cstdint>
#include <math.h>

// ---------------- problem constants ----------------
#define IN_DIM   512
#define OUT_DIM  512
#define BATCH    16384
#define N_KNOTS  12
#define W_TOTAL  576            // 512 spline windows + 64 base windows
#define NTILES   144            // k-tiles of 32 (= 4 windows of 8)
#define NTHREADS 256
#define STAGE_F  6144           // floats per stage: A 4096 + B 2048
#define SMEM_BYTES (2 * STAGE_F * 4)   // 49152 (2 stages -> 4 CTAs/SM)

// ---------------- device scratch ----------------
__device__ float g_knots[IN_DIM * N_KNOTS];
__device__ float g_rden [IN_DIM * (N_KNOTS - 1)];
// A: [tile128][window][1024] fragment-major ; B: [tile64][window][512]
__device__ float g_A[(size_t)(BATCH  / 128) * W_TOTAL * 1024];   // ~288 MB
__device__ float g_B[(size_t)(OUT_DIM / 64)  * W_TOTAL * 512];   // ~9 MB

// ---------------- helpers ----------------
__device__ __forceinline__ float f2tf32(float f) {
    uint32_t o;
    asm("cvt.rna.tf32.f32 %0, %1;" : "=r"(o) : "f"(f));
    return __uint_as_float(o);
}
#define CP16(dst, src) asm volatile("cp.async.cg.shared.global [%0], [%1], 16;" :: "r"(dst), "l"(src) : "memory")
#define CP_COMMIT()    asm volatile("cp.async.commit_group;" ::: "memory")
#define CP_WAIT0()     asm volatile("cp.async.wait_group 0;" ::: "memory")

__device__ __forceinline__ uint32_t smem_u32(const void* p) {
    uint32_t a;
    asm("{ .reg .u64 t; cvta.to.shared.u64 t, %1; cvt.u32.u64 %0, t; }" : "=r"(a) : "l"(p));
    return a;
}
__device__ __forceinline__ void mma4(float* c, float4 a, float b0, float b1) {
    asm volatile(
        "mma.sync.aligned.m16n8k8.row.col.f32.tf32.tf32.f32 "
        "{%0,%1,%2,%3}, {%4,%5,%6,%7}, {%8,%9}, {%0,%1,%2,%3};"
        : "+f"(c[0]), "+f"(c[1]), "+f"(c[2]), "+f"(c[3])
        : "r"(__float_as_uint(a.x)), "r"(__float_as_uint(a.y)),
          "r"(__float_as_uint(a.z)), "r"(__float_as_uint(a.w)),
          "r"(__float_as_uint(b0)), "r"(__float_as_uint(b1)));
}

// degree-3 basis, verbatim reference recursion
__device__ __forceinline__ void eval_basis(float xv, const float* __restrict__ k,
                                           const float* __restrict__ rd,
                                           float* __restrict__ bb)
{
    float t[11];
    #pragma unroll
    for (int j = 0; j < 11; j++)
        t[j] = (xv >= k[j] && xv < k[j + 1]) ? 1.0f : 0.0f;
    #pragma unroll
    for (int j = 0; j < 10; j++)
        t[j] = (xv - k[j]) * rd[j] * t[j] + (k[j + 2] - xv) * rd[j + 1] * t[j + 1];
    #pragma unroll
    for (int j = 0; j < 9; j++)
        t[j] = (xv - k[j]) * rd[j] * t[j] + (k[j + 3] - xv) * rd[j + 2] * t[j + 1];
    #pragma unroll
    for (int j = 0; j < 8; j++)
        bb[j] = f2tf32((xv - k[j]) * rd[j] * t[j] + (k[j + 4] - xv) * rd[j + 3] * t[j + 1]);
}

// ---------------- kernel 1: knot precompute ----------------
__global__ void grid_precompute_kernel(const float* __restrict__ steps_log,
                                       const float* __restrict__ grid_start)
{
    int i = blockIdx.x * blockDim.x + threadIdx.x;
    if (i >= IN_DIM) return;
    float kn[N_KNOTS];
    kn[0] = grid_start[i];
    float acc = kn[0];
    #pragma unroll
    for (int j = 0; j < N_KNOTS - 1; j++) {
        float v  = steps_log[i * (N_KNOTS - 1) + j];
        float sp = fmaxf(v, 0.0f) + log1pf(expf(-fabsf(v)));
        acc += sp;
        kn[j + 1] = acc;
    }
    #pragma unroll
    for (int j = 0; j < N_KNOTS; j++) g_knots[i * N_KNOTS + j] = kn[j];
    #pragma unroll
    for (int j = 0; j < N_KNOTS - 1; j++)
        g_rden[i * (N_KNOTS - 1) + j] = 1.0f / (kn[j + 1] - kn[j] + 1e-8f);
}

// ---------------- kernel 2: weights -> fragment-major 64-col slabs ----------------
__global__ __launch_bounds__(256)
void convert_B_kernel(const float* __restrict__ coeffs,
                      const float* __restrict__ bw)
{
    const int t = threadIdx.x, g = blockIdx.x, Tn = blockIdx.y;
    const int dl = t >> 5, pr = t & 31;           // 8 windows x 32 col-pairs
    const int p16 = pr >> 3, p8 = pr & 7;
    const int o0 = Tn * 64 + p16 * 16 + p8, o1 = o0 + 8;
    float4 a0, a1, b0, b1;
    int window;
    if (g < 64) {
        const int d = g * 8 + dl;
        const float4* p0 = (const float4*)(coeffs + (size_t)o0 * 4096 + d * 8);
        const float4* p1 = (const float4*)(coeffs + (size_t)o1 * 4096 + d * 8);
        a0 = p0[0]; b0 = p0[1]; a1 = p1[0]; b1 = p1[1];
        window = d;
    } else {
        const int w = (g - 64) * 8 + dl;
        const float4* p0 = (const float4*)(bw + (size_t)o0 * 512 + w * 8);
        const float4* p1 = (const float4*)(bw + (size_t)o1 * 512 + w * 8);
        a0 = p0[0]; b0 = p0[1]; a1 = p1[0]; b1 = p1[1];
        window = 512 + w;
    }
    float4* dst = (float4*)(g_B + ((size_t)Tn * W_TOTAL + window) * 512
                            + p16 * 128 + p8 * 16);
    dst[0] = make_float4(f2tf32(a0.x), f2tf32(a1.x), f2tf32(b0.x), f2tf32(b1.x));
    dst[1] = make_float4(f2tf32(a0.y), f2tf32(a1.y), f2tf32(b0.y), f2tf32(b1.y));
    dst[2] = make_float4(f2tf32(a0.z), f2tf32(a1.z), f2tf32(b0.z), f2tf32(b1.z));
    dst[3] = make_float4(f2tf32(a0.w), f2tf32(a1.w), f2tf32(b0.w), f2tf32(b1.w));
}

// ---------------- kernel 3: A slabs (basis + silu), direct fragment writes ----------------
__global__ __launch_bounds__(256)
void gen_A_kernel(const float* __restrict__ x)
{
    __shared__ float sh[128 * 65];
    const int t = threadIdx.x, g = blockIdx.x, Tm = blockIdx.y;

    if (g < 64) {
        float* xs = sh;                         // [row][dl] stride 9
        float* kk = sh + 1152;
        float* rr = sh + 1152 + 96;
        #pragma unroll
        for (int it = 0; it < 4; it++) {
            const int idx = it * 256 + t;
            const int row = idx >> 3, dl = idx & 7;
            xs[row * 9 + dl] = __ldg(x + (size_t)(Tm * 128 + row) * IN_DIM + g * 8 + dl);
        }
        if (t < 96)               kk[t]      = g_knots[g * 8 * N_KNOTS + t];
        else if (t < 96 + 88)     rr[t - 96] = g_rden[g * 8 * (N_KNOTS - 1) + (t - 96)];
        __syncthreads();

        #pragma unroll
        for (int m = 0; m < 2; m++) {
            const int i  = m * 256 + t;
            const int dl = i >> 6, pr = i & 63;
            const int p16 = pr >> 3, p8 = pr & 7;
            const int row0 = p16 * 16 + p8;
            float bb0[8], bb1[8];
            eval_basis(xs[row0 * 9 + dl],       kk + dl * 12, rr + dl * 11, bb0);
            eval_basis(xs[(row0 + 8) * 9 + dl], kk + dl * 12, rr + dl * 11, bb1);
            float4* dst = (float4*)(g_A + ((size_t)Tm * W_TOTAL + g * 8 + dl) * 1024
                                    + p16 * 128 + p8 * 16);
            #pragma unroll
            for (int j = 0; j < 4; j++)
                dst[j] = make_float4(bb0[j], bb1[j], bb0[j + 4], bb1[j + 4]);
        }
    } else {
        const int d0 = (g - 64) * 64;
        #pragma unroll
        for (int it = 0; it < 32; it++) {
            const int idx = it * 256 + t;
            const int row = idx >> 6, dd = idx & 63;
            sh[row * 65 + dd] = __ldg(x + (size_t)(Tm * 128 + row) * IN_DIM + d0 + dd);
        }
        __syncthreads();

        #pragma unroll
        for (int m = 0; m < 2; m++) {
            const int i  = m * 256 + t;
            const int wl = i >> 6, pr = i & 63;
            const int p16 = pr >> 3, p8 = pr & 7;
            const int row0 = p16 * 16 + p8;
            float s0[8], s1[8];
            #pragma unroll
            for (int c = 0; c < 8; c++) {
                const float v0 = sh[row0 * 65 + wl * 8 + c];
                const float v1 = sh[(row0 + 8) * 65 + wl * 8 + c];
                s0[c] = f2tf32(v0 / (1.0f + expf(-v0)));
                s1[c] = f2tf32(v1 / (1.0f + expf(-v1)));
            }
            float4* dst = (float4*)(g_A + ((size_t)Tm * W_TOTAL + 512 + (g - 64) * 8 + wl) * 1024
                                    + p16 * 128 + p8 * 16);
            #pragma unroll
            for (int j = 0; j < 4; j++)
                dst[j] = make_float4(s0[j], s1[j], s0[j + 4], s1[j + 4]);
        }
    }
}

// ---------------- kernel 4: tf32 GEMM, CTA 128x64, warp 32x32, 4 CTAs/SM ----------------
__global__ __launch_bounds__(NTHREADS, 4)
void kan_gemm_kernel(const float* __restrict__ x,
                     const float* __restrict__ res_scale,
                     float* __restrict__ out)
{
    extern __shared__ float smem[];
    const int t = threadIdx.x, warp = t >> 5, lane = t & 31;
    const int q = lane >> 2, r = lane & 3;
    const int warpM = warp >> 1, warpN = warp & 1;        // 4 x 2 warps, 32x32 tiles
    const int Tn = blockIdx.x, Tm = blockIdx.y;           // Tn fastest -> A L2 reuse
    const int m_blk = Tm * 128, n_blk = Tn * 64;

    const float* Ab = g_A + (size_t)Tm * (W_TOTAL * 1024);
    const float* Bb = g_B + (size_t)Tn * (W_TOTAL * 512);
    const uint32_t sb = smem_u32(smem);

    // per-warp smem read offsets (floats)
    const int aoff0 = (warpM * 2 + 0) * 128 + lane * 4;
    const int aoff1 = (warpM * 2 + 1) * 128 + lane * 4;
    const int boff0 = (warpN * 2 + 0) * 128 + lane * 4;
    const int boff1 = (warpN * 2 + 1) * 128 + lane * 4;

    auto loader = [&](int kt, int stage) {
        const float* as = Ab + (size_t)kt * 4096;
        const float* bs = Bb + (size_t)kt * 2048;
        const uint32_t sa = sb + stage * (STAGE_F * 4);
        #pragma unroll
        for (int i = 0; i < 4; i++) CP16(sa + (i * 256 + t) * 16, as + (i * 256 + t) * 4);
        #pragma unroll
        for (int i = 0; i < 2; i++) CP16(sa + 16384 + (i * 256 + t) * 16, bs + (i * 256 + t) * 4);
        CP_COMMIT();
    };

    float acc[2][4][4];
    #pragma unroll
    for (int i = 0; i < 2; i++)
        #pragma unroll
        for (int j = 0; j < 4; j++)
            #pragma unroll
            for (int v = 0; v < 4; v++) acc[i][j][v] = 0.0f;

    loader(0, 0);

    auto tile_step = [&](int kt, int stage) {
        CP_WAIT0();              // group issued last iteration has landed
        __syncthreads();         // all warps done computing the stage we overwrite
        if (kt + 1 < NTILES) loader(kt + 1, stage ^ 1);

        const float* As = smem + stage * STAGE_F;
        const float* Bs = As + 4096;
        #pragma unroll
        for (int ws = 0; ws < 4; ws++) {
            const float4 a0 = *(const float4*)(As + ws * 1024 + aoff0);
            const float4 a1 = *(const float4*)(As + ws * 1024 + aoff1);
            const float4 b0 = *(const float4*)(Bs + ws * 512 + boff0);
            const float4 b1 = *(const float4*)(Bs + ws * 512 + boff1);
            mma4(acc[0][0], a0, b0.x, b0.z); mma4(acc[0][1], a0, b0.y, b0.w);
            mma4(acc[0][2], a0, b1.x, b1.z); mma4(acc[0][3], a0, b1.y, b1.w);
            mma4(acc[1][0], a1, b0.x, b0.z); mma4(acc[1][1], a1, b0.y, b0.w);
            mma4(acc[1][2], a1, b1.x, b1.z); mma4(acc[1][3], a1, b1.y, b1.w);
        }
    };

    #pragma unroll 1
    for (int kt = 0; kt < NTILES; kt += 2) {   // 144 % 2 == 0
        tile_step(kt,     0);
        tile_step(kt + 1, 1);
    }

    // ---- epilogue: + rs*x, tanh ----
    const float rs = __ldg(res_scale);
    #pragma unroll
    for (int mf = 0; mf < 2; mf++) {
        #pragma unroll
        for (int rr2 = 0; rr2 < 2; rr2++) {
            const int rowg = m_blk + warpM * 32 + mf * 16 + rr2 * 8 + q;
            #pragma unroll
            for (int nf = 0; nf < 4; nf++) {
                const int col = n_blk + warpN * 32 + nf * 8 + r * 2;
                const size_t idx = (size_t)rowg * OUT_DIM + col;
                const float2 xv = __ldg((const float2*)(x + idx));
                float2 o;
                o.x = tanhf(acc[mf][nf][rr2 * 2 + 0] + rs * xv.x);
                o.y = tanhf(acc[mf][nf][rr2 * 2 + 1] + rs * xv.y);
                *(float2*)(out + idx) = o;
            }
        }
    }
}

// ---------------------------------------------------------------------------
extern "C" void kernel_launch(void* const* d_in, const int* in_sizes, int n_in,
                              void* d_out, int out_size)
{
    const float* x           = (const float*)d_in[0];
    const float* coeffs      = (const float*)d_in[1];
    const float* base_weight = (const float*)d_in[2];
    const float* steps_log   = (const float*)d_in[3];
    const float* grid_start  = (const float*)d_in[4];
    const float* res_scale   = (const float*)d_in[5];
    float* out = (float*)d_out;

    grid_precompute_kernel<<<2, 256>>>(steps_log, grid_start);
    convert_B_kernel<<<dim3(72, 8), 256>>>(coeffs, base_weight);
    gen_A_kernel<<<dim3(72, 128), 256>>>(x);

    cudaFuncSetAttribute(kan_gemm_kernel,
                         cudaFuncAttributeMaxDynamicSharedMemorySize, SMEM_BYTES);
    kan_gemm_kernel<<<dim3(8, 128), NTHREADS, SMEM_BYTES>>>(x, res_scale, out);
}

// round 17
// speedup vs baseline: 1.0291x; 1.0291x over previous
#include <cuda_runtime.h>
#include <cuda_bf16.h>
#include <cstdint>
#include <math.h>

// ---------------- problem constants ----------------
#define IN_DIM   512
#define OUT_DIM  512
#define BATCH    16384
#define N_KNOTS  12
#define W_TOTAL  576            // 512 spline windows + 64 base windows
#define NTILES   144            // k-tiles of 32 (= 4 windows of 8)
#define GEMM_THREADS 128        // 4 warps of 64x32
#define STAGE_F  6144           // floats per stage: A 4096 + B 2048
#define SMEM_BYTES (2 * STAGE_F * 4)   // 49152 (2 stages -> 4 CTAs/SM)

// ---------------- device scratch ----------------
__device__ float g_knots[IN_DIM * N_KNOTS];
__device__ float g_rden [IN_DIM * (N_KNOTS - 1)];
// A: [tile128][window][1024] fragment-major ; B: [tile64][window][512]
__device__ float g_A[(size_t)(BATCH  / 128) * W_TOTAL * 1024];   // ~288 MB
__device__ float g_B[(size_t)(OUT_DIM / 64)  * W_TOTAL * 512];   // ~9 MB

// ---------------- helpers ----------------
__device__ __forceinline__ float f2tf32(float f) {
    uint32_t o;
    asm("cvt.rna.tf32.f32 %0, %1;" : "=r"(o) : "f"(f));
    return __uint_as_float(o);
}
#define CP16(dst, src) asm volatile("cp.async.cg.shared.global [%0], [%1], 16;" :: "r"(dst), "l"(src) : "memory")
#define CP_COMMIT()    asm volatile("cp.async.commit_group;" ::: "memory")
#define CP_WAIT0()     asm volatile("cp.async.wait_group 0;" ::: "memory")

__device__ __forceinline__ uint32_t smem_u32(const void* p) {
    uint32_t a;
    asm("{ .reg .u64 t; cvta.to.shared.u64 t, %1; cvt.u32.u64 %0, t; }" : "=r"(a) : "l"(p));
    return a;
}
__device__ __forceinline__ void mma4(float* c, float4 a, float b0, float b1) {
    asm volatile(
        "mma.sync.aligned.m16n8k8.row.col.f32.tf32.tf32.f32 "
        "{%0,%1,%2,%3}, {%4,%5,%6,%7}, {%8,%9}, {%0,%1,%2,%3};"
        : "+f"(c[0]), "+f"(c[1]), "+f"(c[2]), "+f"(c[3])
        : "r"(__float_as_uint(a.x)), "r"(__float_as_uint(a.y)),
          "r"(__float_as_uint(a.z)), "r"(__float_as_uint(a.w)),
          "r"(__float_as_uint(b0)), "r"(__float_as_uint(b1)));
}

// degree-3 basis, verbatim reference recursion
__device__ __forceinline__ void eval_basis(float xv, const float* __restrict__ k,
                                           const float* __restrict__ rd,
                                           float* __restrict__ bb)
{
    float t[11];
    #pragma unroll
    for (int j = 0; j < 11; j++)
        t[j] = (xv >= k[j] && xv < k[j + 1]) ? 1.0f : 0.0f;
    #pragma unroll
    for (int j = 0; j < 10; j++)
        t[j] = (xv - k[j]) * rd[j] * t[j] + (k[j + 2] - xv) * rd[j + 1] * t[j + 1];
    #pragma unroll
    for (int j = 0; j < 9; j++)
        t[j] = (xv - k[j]) * rd[j] * t[j] + (k[j + 3] - xv) * rd[j + 2] * t[j + 1];
    #pragma unroll
    for (int j = 0; j < 8; j++)
        bb[j] = f2tf32((xv - k[j]) * rd[j] * t[j] + (k[j + 4] - xv) * rd[j + 3] * t[j + 1]);
}

// ---------------- kernel 1: knot precompute ----------------
__global__ void grid_precompute_kernel(const float* __restrict__ steps_log,
                                       const float* __restrict__ grid_start)
{
    int i = blockIdx.x * blockDim.x + threadIdx.x;
    if (i >= IN_DIM) return;
    float kn[N_KNOTS];
    kn[0] = grid_start[i];
    float acc = kn[0];
    #pragma unroll
    for (int j = 0; j < N_KNOTS - 1; j++) {
        float v  = steps_log[i * (N_KNOTS - 1) + j];
        float sp = fmaxf(v, 0.0f) + log1pf(expf(-fabsf(v)));
        acc += sp;
        kn[j + 1] = acc;
    }
    #pragma unroll
    for (int j = 0; j < N_KNOTS; j++) g_knots[i * N_KNOTS + j] = kn[j];
    #pragma unroll
    for (int j = 0; j < N_KNOTS - 1; j++)
        g_rden[i * (N_KNOTS - 1) + j] = 1.0f / (kn[j + 1] - kn[j] + 1e-8f);
}

// ---------------- kernel 2: weights -> fragment-major 64-col slabs ----------------
__global__ __launch_bounds__(256)
void convert_B_kernel(const float* __restrict__ coeffs,
                      const float* __restrict__ bw)
{
    const int t = threadIdx.x, g = blockIdx.x, Tn = blockIdx.y;
    const int dl = t >> 5, pr = t & 31;           // 8 windows x 32 col-pairs
    const int p16 = pr >> 3, p8 = pr & 7;
    const int o0 = Tn * 64 + p16 * 16 + p8, o1 = o0 + 8;
    float4 a0, a1, b0, b1;
    int window;
    if (g < 64) {
        const int d = g * 8 + dl;
        const float4* p0 = (const float4*)(coeffs + (size_t)o0 * 4096 + d * 8);
        const float4* p1 = (const float4*)(coeffs + (size_t)o1 * 4096 + d * 8);
        a0 = p0[0]; b0 = p0[1]; a1 = p1[0]; b1 = p1[1];
        window = d;
    } else {
        const int w = (g - 64) * 8 + dl;
        const float4* p0 = (const float4*)(bw + (size_t)o0 * 512 + w * 8);
        const float4* p1 = (const float4*)(bw + (size_t)o1 * 512 + w * 8);
        a0 = p0[0]; b0 = p0[1]; a1 = p1[0]; b1 = p1[1];
        window = 512 + w;
    }
    float4* dst = (float4*)(g_B + ((size_t)Tn * W_TOTAL + window) * 512
                            + p16 * 128 + p8 * 16);
    dst[0] = make_float4(f2tf32(a0.x), f2tf32(a1.x), f2tf32(b0.x), f2tf32(b1.x));
    dst[1] = make_float4(f2tf32(a0.y), f2tf32(a1.y), f2tf32(b0.y), f2tf32(b1.y));
    dst[2] = make_float4(f2tf32(a0.z), f2tf32(a1.z), f2tf32(b0.z), f2tf32(b1.z));
    dst[3] = make_float4(f2tf32(a0.w), f2tf32(a1.w), f2tf32(b0.w), f2tf32(b1.w));
}

// ---------------- kernel 3: A slabs (basis + silu), direct fragment writes ----------------
__global__ __launch_bounds__(256)
void gen_A_kernel(const float* __restrict__ x)
{
    __shared__ float sh[128 * 65];
    const int t = threadIdx.x, g = blockIdx.x, Tm = blockIdx.y;

    if (g < 64) {
        float* xs = sh;                         // [row][dl] stride 9
        float* kk = sh + 1152;
        float* rr = sh + 1152 + 96;
        #pragma unroll
        for (int it = 0; it < 4; it++) {
            const int idx = it * 256 + t;
            const int row = idx >> 3, dl = idx & 7;
            xs[row * 9 + dl] = __ldg(x + (size_t)(Tm * 128 + row) * IN_DIM + g * 8 + dl);
        }
        if (t < 96)               kk[t]      = g_knots[g * 8 * N_KNOTS + t];
        else if (t < 96 + 88)     rr[t - 96] = g_rden[g * 8 * (N_KNOTS - 1) + (t - 96)];
        __syncthreads();

        #pragma unroll
        for (int m = 0; m < 2; m++) {
            const int i  = m * 256 + t;
            const int dl = i >> 6, pr = i & 63;
            const int p16 = pr >> 3, p8 = pr & 7;
            const int row0 = p16 * 16 + p8;
            float bb0[8], bb1[8];
            eval_basis(xs[row0 * 9 + dl],       kk + dl * 12, rr + dl * 11, bb0);
            eval_basis(xs[(row0 + 8) * 9 + dl], kk + dl * 12, rr + dl * 11, bb1);
            float4* dst = (float4*)(g_A + ((size_t)Tm * W_TOTAL + g * 8 + dl) * 1024
                                    + p16 * 128 + p8 * 16);
            #pragma unroll
            for (int j = 0; j < 4; j++)
                dst[j] = make_float4(bb0[j], bb1[j], bb0[j + 4], bb1[j + 4]);
        }
    } else {
        const int d0 = (g - 64) * 64;
        #pragma unroll
        for (int it = 0; it < 32; it++) {
            const int idx = it * 256 + t;
            const int row = idx >> 6, dd = idx & 63;
            sh[row * 65 + dd] = __ldg(x + (size_t)(Tm * 128 + row) * IN_DIM + d0 + dd);
        }
        __syncthreads();

        #pragma unroll
        for (int m = 0; m < 2; m++) {
            const int i  = m * 256 + t;
            const int wl = i >> 6, pr = i & 63;
            const int p16 = pr >> 3, p8 = pr & 7;
            const int row0 = p16 * 16 + p8;
            float s0[8], s1[8];
            #pragma unroll
            for (int c = 0; c < 8; c++) {
                const float v0 = sh[row0 * 65 + wl * 8 + c];
                const float v1 = sh[(row0 + 8) * 65 + wl * 8 + c];
                s0[c] = f2tf32(v0 / (1.0f + expf(-v0)));
                s1[c] = f2tf32(v1 / (1.0f + expf(-v1)));
            }
            float4* dst = (float4*)(g_A + ((size_t)Tm * W_TOTAL + 512 + (g - 64) * 8 + wl) * 1024
                                    + p16 * 128 + p8 * 16);
            #pragma unroll
            for (int j = 0; j < 4; j++)
                dst[j] = make_float4(s0[j], s1[j], s0[j + 4], s1[j + 4]);
        }
    }
}

// ---------------- kernel 4: tf32 GEMM, CTA 128x64, 4 warps of 64x32, 4 CTAs/SM ----------------
__global__ __launch_bounds__(GEMM_THREADS, 4)
void kan_gemm_kernel(const float* __restrict__ x,
                     const float* __restrict__ res_scale,
                     float* __restrict__ out)
{
    extern __shared__ float smem[];
    const int t = threadIdx.x, warp = t >> 5, lane = t & 31;
    const int q = lane >> 2, r = lane & 3;
    const int warpM = warp >> 1, warpN = warp & 1;        // 2 x 2 warps, 64x32 tiles
    const int Tn = blockIdx.x, Tm = blockIdx.y;           // Tn fastest -> A L2 reuse
    const int m_blk = Tm * 128, n_blk = Tn * 64;

    const float* Ab = g_A + (size_t)Tm * (W_TOTAL * 1024);
    const float* Bb = g_B + (size_t)Tn * (W_TOTAL * 512);
    const uint32_t sb = smem_u32(smem);

    // per-warp smem read offsets (floats): A rows warpM*64..+63, B cols warpN*32..+31
    const int aoff = warpM * 4 * 128 + lane * 4;          // + mi*128
    const int boff = warpN * 2 * 128 + lane * 4;          // + j*128

    auto loader = [&](int kt, int stage) {
        const float* as = Ab + (size_t)kt * 4096;
        const float* bs = Bb + (size_t)kt * 2048;
        const uint32_t sa = sb + stage * (STAGE_F * 4);
        #pragma unroll
        for (int i = 0; i < 8; i++) CP16(sa + (i * 128 + t) * 16, as + (i * 128 + t) * 4);
        #pragma unroll
        for (int i = 0; i < 4; i++) CP16(sa + 16384 + (i * 128 + t) * 16, bs + (i * 128 + t) * 4);
        CP_COMMIT();
    };

    float acc[4][4][4];                                   // [mi][nf][frag]
    #pragma unroll
    for (int i = 0; i < 4; i++)
        #pragma unroll
        for (int j = 0; j < 4; j++)
            #pragma unroll
            for (int v = 0; v < 4; v++) acc[i][j][v] = 0.0f;

    loader(0, 0);

    auto tile_step = [&](int kt, int stage) {
        CP_WAIT0();              // group issued last iteration has landed
        __syncthreads();         // all warps done computing the stage we overwrite
        if (kt + 1 < NTILES) loader(kt + 1, stage ^ 1);

        const float* As = smem + stage * STAGE_F;
        const float* Bs = As + 4096;
        #pragma unroll
        for (int ws = 0; ws < 4; ws++) {
            float4 a[4];
            #pragma unroll
            for (int mi = 0; mi < 4; mi++)
                a[mi] = *(const float4*)(As + ws * 1024 + aoff + mi * 128);
            const float4 b0 = *(const float4*)(Bs + ws * 512 + boff);
            const float4 b1 = *(const float4*)(Bs + ws * 512 + boff + 128);
            #pragma unroll
            for (int mi = 0; mi < 4; mi++) {
                mma4(acc[mi][0], a[mi], b0.x, b0.z);
                mma4(acc[mi][1], a[mi], b0.y, b0.w);
                mma4(acc[mi][2], a[mi], b1.x, b1.z);
                mma4(acc[mi][3], a[mi], b1.y, b1.w);
            }
        }
    };

    #pragma unroll 1
    for (int kt = 0; kt < NTILES; kt += 2) {   // 144 % 2 == 0
        tile_step(kt,     0);
        tile_step(kt + 1, 1);
    }

    // ---- epilogue: + rs*x, tanh ----
    const float rs = __ldg(res_scale);
    #pragma unroll
    for (int mi = 0; mi < 4; mi++) {
        #pragma unroll
        for (int rr2 = 0; rr2 < 2; rr2++) {
            const int rowg = m_blk + warpM * 64 + mi * 16 + rr2 * 8 + q;
            #pragma unroll
            for (int nf = 0; nf < 4; nf++) {
                const int col = n_blk + warpN * 32 + nf * 8 + r * 2;
                const size_t idx = (size_t)rowg * OUT_DIM + col;
                const float2 xv = __ldg((const float2*)(x + idx));
                float2 o;
                o.x = tanhf(acc[mi][nf][rr2 * 2 + 0] + rs * xv.x);
                o.y = tanhf(acc[mi][nf][rr2 * 2 + 1] + rs * xv.y);
                *(float2*)(out + idx) = o;
            }
        }
    }
}

// ---------------------------------------------------------------------------
extern "C" void kernel_launch(void* const* d_in, const int* in_sizes, int n_in,
                              void* d_out, int out_size)
{
    const float* x           = (const float*)d_in[0];
    const float* coeffs      = (const float*)d_in[1];
    const float* base_weight = (const float*)d_in[2];
    const float* steps_log   = (const float*)d_in[3];
    const float* grid_start  = (const float*)d_in[4];
    const float* res_scale   = (const float*)d_in[5];
    float* out = (float*)d_out;

    grid_precompute_kernel<<<2, 256>>>(steps_log, grid_start);
    convert_B_kernel<<<dim3(72, 8), 256>>>(coeffs, base_weight);
    gen_A_kernel<<<dim3(72, 128), 256>>>(x);

    cudaFuncSetAttribute(kan_gemm_kernel,
                         cudaFuncAttributeMaxDynamicSharedMemorySize, SMEM_BYTES);
    kan_gemm_kernel<<<dim3(8, 128), GEMM_THREADS, SMEM_BYTES>>>(x, res_scale, out);
}